// round 11
// baseline (speedup 1.0000x reference)
#include <cuda_runtime.h>
#include <cuda_fp16.h>
#include <cstdint>

#define B_   32
#define C_   256
#define H_   128
#define W_   128
#define R_   128
#define F_   256
#define HP   126
#define WP   126
#define HW_  (H_ * W_)

// ---- device scratch (allocation-free) -----------------------------------
__device__ __half g_yh[(size_t)B_ * R_ * H_ * W_];     // fp16 134 MB
__device__ __half g_f3h[128 * 256];                    // f3^T [r][c]
__device__ __half g_f0h[256 * 128];                    // f0   [f][r]

// ---- PTX helpers --------------------------------------------------------
__device__ __forceinline__ uint32_t smem_u32(const void* p) {
    uint32_t a;
    asm("{ .reg .u64 t; cvta.to.shared.u64 t, %1; cvt.u32.u64 %0, t; }"
        : "=r"(a) : "l"(p));
    return a;
}
__device__ __forceinline__ void ldsm_x4(uint32_t* r, uint32_t addr) {
    asm volatile("ldmatrix.sync.aligned.m8n8.x4.shared.b16 {%0,%1,%2,%3}, [%4];"
                 : "=r"(r[0]), "=r"(r[1]), "=r"(r[2]), "=r"(r[3]) : "r"(addr));
}
__device__ __forceinline__ void ldsm_x4t(uint32_t* r, uint32_t addr) {
    asm volatile("ldmatrix.sync.aligned.m8n8.x4.trans.shared.b16 {%0,%1,%2,%3}, [%4];"
                 : "=r"(r[0]), "=r"(r[1]), "=r"(r[2]), "=r"(r[3]) : "r"(addr));
}
__device__ __forceinline__ void mma16816(float* c, const uint32_t* a,
                                         const uint32_t* b) {
    asm volatile(
        "mma.sync.aligned.m16n8k16.row.col.f32.f16.f16.f32 "
        "{%0,%1,%2,%3}, {%4,%5,%6,%7}, {%8,%9}, {%0,%1,%2,%3};"
        : "+f"(c[0]), "+f"(c[1]), "+f"(c[2]), "+f"(c[3])
        : "r"(a[0]), "r"(a[1]), "r"(a[2]), "r"(a[3]), "r"(b[0]), "r"(b[1]));
}

#define A_LD  24    // halves per A smem row (16 + 8 pad) -> 48B stride
#define B3_LD 136   // K3 B row: 128 + 8 pad halves
#define B1_LD 264   // K1 B row: 256 + 8 pad halves
#define ST_LD 132   // floats per staged K3 output row

#define DSMEM_BYTES 69632   // 68 KB dynamic smem (pipeline / staging overlay)

// =========================================================================
// Setup: f0 -> fp16 [f][r] ; f3 transpose -> fp16 [r][c]
// =========================================================================
__global__ void ksplit_weights(const float* __restrict__ f0,
                               const float* __restrict__ f3) {
    int i = blockIdx.x * 256 + threadIdx.x;
    if (i < 256 * 128) g_f0h[i] = __float2half_rn(f0[i]);
    if (i < 128 * 256) {
        int m = i >> 8, k = i & 255;
        g_f3h[m * 256 + k] = __float2half_rn(f3[k * 128 + m]);
    }
}

// =========================================================================
// K1: y[b,r,h,w] = sum_c f3t[r,c] x[b,c,h,w]   (y fp16)
// block: M=128 (r), N=256 (2 h-rows), K=256, chunks of 16
// 512 threads, warps 4m x 4n, warp tile 32x64, 2-stage reg prefetch
// Epilogue: stage in smem, 512B contiguous row writes.
// =========================================================================
__global__ __launch_bounds__(512, 1)
void k1_mma(const float* __restrict__ x) {
    extern __shared__ char dsm[];
    __half* Ah = (__half*)dsm;                 // 2 stages: 128*A_LD each
    __half* Bh = Ah + 2 * 128 * A_LD;          // 2 stages: 16*B1_LD each

    const int tid = threadIdx.x, wid = tid >> 5, lane = tid & 31;
    const int b = blockIdx.y, h0 = blockIdx.x * 2;
    const int wm = wid & 3, wn = wid >> 2;
    const float* xb = x + ((size_t)b * C_) * HW_ + (size_t)h0 * W_;

    float acc[2][8][4];
#pragma unroll
    for (int i = 0; i < 2; ++i)
#pragma unroll
        for (int j = 0; j < 8; ++j)
#pragma unroll
            for (int q = 0; q < 4; ++q) acc[i][j][q] = 0.f;

    const int am = tid >> 1, akh = (tid & 1) * 8;
    const int bk = tid >> 5, bn8 = (tid & 31) * 8;

    {
        if (tid < 256)
            *(uint4*)&Ah[am * A_LD + akh] = *(const uint4*)&g_f3h[am * 256 + akh];
        float4 v0 = *(const float4*)(xb + (size_t)bk * HW_ + bn8);
        float4 v1 = *(const float4*)(xb + (size_t)bk * HW_ + bn8 + 4);
        __half2 p0 = __floats2half2_rn(v0.x, v0.y), p1 = __floats2half2_rn(v0.z, v0.w);
        __half2 p2 = __floats2half2_rn(v1.x, v1.y), p3 = __floats2half2_rn(v1.z, v1.w);
        uint4 w = make_uint4(*(uint32_t*)&p0, *(uint32_t*)&p1,
                             *(uint32_t*)&p2, *(uint32_t*)&p3);
        *(uint4*)&Bh[bk * B1_LD + bn8] = w;
    }
    __syncthreads();

    const uint32_t aBase = smem_u32(Ah);
    const uint32_t bBase = smem_u32(Bh);
    const int arow = wm * 32 + (lane & 15);
    const int acol = (lane >> 4) * 8;
    const int brow = (lane & 7) + ((lane >> 3) & 1) * 8;
    const int bcol = wn * 64 + ((lane >> 4) & 1) * 8;

    int cur = 0;
#pragma unroll 1
    for (int kc = 0; kc < 16; ++kc) {
        uint4 pa; float4 pb0, pb1;
        const bool more = (kc + 1) < 16;
        if (more) {
            int c0n = (kc + 1) * 16;
            if (tid < 256) pa = *(const uint4*)&g_f3h[am * 256 + c0n + akh];
            pb0 = *(const float4*)(xb + (size_t)(c0n + bk) * HW_ + bn8);
            pb1 = *(const float4*)(xb + (size_t)(c0n + bk) * HW_ + bn8 + 4);
        }

        uint32_t a[2][4];
        const uint32_t aS = aBase + cur * (128 * A_LD * 2);
#pragma unroll
        for (int mf = 0; mf < 2; ++mf)
            ldsm_x4(a[mf], aS + ((arow + mf * 16) * A_LD + acol) * 2);
        const uint32_t bS = bBase + cur * (16 * B1_LD * 2);
#pragma unroll
        for (int g = 0; g < 4; ++g) {
            uint32_t bf[4];
            ldsm_x4t(bf, bS + (brow * B1_LD + bcol + g * 16) * 2);
#pragma unroll
            for (int mf = 0; mf < 2; ++mf) {
                mma16816(acc[mf][g * 2 + 0], a[mf], bf + 0);
                mma16816(acc[mf][g * 2 + 1], a[mf], bf + 2);
            }
        }

        if (more) {
            int nxt = cur ^ 1;
            if (tid < 256) *(uint4*)&Ah[nxt * (128 * A_LD) + am * A_LD + akh] = pa;
            __half2 p0 = __floats2half2_rn(pb0.x, pb0.y), p1 = __floats2half2_rn(pb0.z, pb0.w);
            __half2 p2 = __floats2half2_rn(pb1.x, pb1.y), p3 = __floats2half2_rn(pb1.z, pb1.w);
            uint4 w = make_uint4(*(uint32_t*)&p0, *(uint32_t*)&p1,
                                 *(uint32_t*)&p2, *(uint32_t*)&p3);
            *(uint4*)&Bh[nxt * (16 * B1_LD) + bk * B1_LD + bn8] = w;
            __syncthreads();
            cur = nxt;
        }
    }

    // epilogue: stage (128 r x 256 n halves), then 512B contiguous rows
    __syncthreads();
    __half* sy = (__half*)dsm;            // 128*B1_LD*2 = 67584 B
    const int r0 = wm * 32, n0 = wn * 64;
    const int lr = lane >> 2, lc = (lane & 3) * 2;
#pragma unroll
    for (int mf = 0; mf < 2; ++mf)
#pragma unroll
        for (int g = 0; g < 8; ++g) {
            int r = r0 + mf * 16 + lr;
            int n = n0 + g * 8 + lc;
            __half2 v0 = __floats2half2_rn(acc[mf][g][0], acc[mf][g][1]);
            __half2 v1 = __floats2half2_rn(acc[mf][g][2], acc[mf][g][3]);
            *(__half2*)&sy[r * B1_LD + n] = v0;
            *(__half2*)&sy[(r + 8) * B1_LD + n] = v1;
        }
    __syncthreads();
#pragma unroll
    for (int i = 0; i < 8; ++i) {
        int r = wid * 8 + i;
        uint4 v = *(const uint4*)&sy[r * B1_LD + lane * 8];
        *(uint4*)(g_yh + (((size_t)b * R_ + r) * H_ + h0) * W_ + lane * 8) = v;
    }
}

// =========================================================================
// K3 fused: out[b,f,p,q] = sum_r f0[f,r] * z[b,r,p,q]
// where z is computed ON THE FLY from y (separable 3x3 depthwise).
// block: 256 threads, warps 4m x 2n, warp tile 32x64, tile 128x128,
// K=128 chunks of 16, 2-stage manual double buffer with reg prefetch.
// B loader: thread -> (r-row br, 8 q's): reads y rows p..p+2, computes z fp16.
// =========================================================================
__global__ __launch_bounds__(256, 2)
void k3_fused(const float* __restrict__ f1, const float* __restrict__ f2,
              float* __restrict__ out) {
    extern __shared__ char dsm[];
    __half* Ah = (__half*)dsm;                 // 2 stages: 128*A_LD
    __half* Bh = Ah + 2 * 128 * A_LD;          // 2 stages: 16*B3_LD

    const int tid = threadIdx.x, wid = tid >> 5, lane = tid & 31;
    const int p = blockIdx.x, m0 = blockIdx.y * 128, b = blockIdx.z;
    const int wm = wid & 3, wn = wid >> 2;

    float acc[2][8][4];
#pragma unroll
    for (int i = 0; i < 2; ++i)
#pragma unroll
        for (int j = 0; j < 8; ++j)
#pragma unroll
            for (int q = 0; q < 4; ++q) acc[i][j][q] = 0.f;

    const int am = tid >> 1, akh = (tid & 1) * 8;   // A loader
    const int br = tid >> 4, q8 = (tid & 15) * 8;   // B loader: r-row, q group
    const bool qedge = (q8 == 120);

    // depthwise compute from raw y regs -> packed fp16 z
    auto compute_z = [&](const uint4 yr[3], const uint32_t ye[3],
                         const float w0, const float w1, const float w2,
                         const float v0, const float v1, const float v2,
                         uint4& zw) {
        float z[8];
#pragma unroll
        for (int j = 0; j < 8; ++j) z[j] = 0.f;
#pragma unroll
        for (int a = 0; a < 3; ++a) {
            float t[10];
            const __half2* hp = (const __half2*)&yr[a];
#pragma unroll
            for (int j = 0; j < 4; ++j) {
                float2 f = __half22float2(hp[j]);
                t[j * 2] = f.x; t[j * 2 + 1] = f.y;
            }
            float2 fe = __half22float2(*(const __half2*)&ye[a]);
            t[8] = fe.x; t[9] = fe.y;
            const float va = (a == 0) ? v0 : ((a == 1) ? v1 : v2);
#pragma unroll
            for (int j = 0; j < 8; ++j)
                z[j] += va * (t[j] * w0 + t[j + 1] * w1 + t[j + 2] * w2);
        }
        if (qedge) { z[6] = 0.f; z[7] = 0.f; }
        __half2 o0 = __floats2half2_rn(z[0], z[1]), o1 = __floats2half2_rn(z[2], z[3]);
        __half2 o2 = __floats2half2_rn(z[4], z[5]), o3 = __floats2half2_rn(z[6], z[7]);
        zw = make_uint4(*(uint32_t*)&o0, *(uint32_t*)&o1,
                        *(uint32_t*)&o2, *(uint32_t*)&o3);
    };

    // load y window for r-chunk kc into regs
    auto load_y = [&](int kc, uint4 yr[3], uint32_t ye[3],
                      float& w0, float& w1, float& w2,
                      float& v0, float& v1, float& v2) {
        const int r = kc * 16 + br;
        const __half* yb = g_yh + ((((size_t)b * R_) + r) * H_ + p) * W_ + q8;
#pragma unroll
        for (int a = 0; a < 3; ++a) {
            yr[a] = *(const uint4*)(yb + a * W_);
            if (!qedge) ye[a] = *(const uint32_t*)(yb + a * W_ + 8);
            else        ye[a] = 0u;
        }
        w0 = f2[r]; w1 = f2[128 + r]; w2 = f2[256 + r];
        v0 = f1[r]; v1 = f1[128 + r]; v2 = f1[256 + r];
    };

    // preload chunk 0
    {
        *(uint4*)&Ah[am * A_LD + akh] = *(const uint4*)&g_f0h[(m0 + am) * 128 + akh];
        uint4 yr[3]; uint32_t ye[3]; float w0, w1, w2, v0, v1, v2; uint4 zw;
        load_y(0, yr, ye, w0, w1, w2, v0, v1, v2);
        compute_z(yr, ye, w0, w1, w2, v0, v1, v2, zw);
        *(uint4*)&Bh[br * B3_LD + q8] = zw;
    }
    __syncthreads();

    const uint32_t aBase = smem_u32(Ah);
    const uint32_t bBase = smem_u32(Bh);
    const int arow = wm * 32 + (lane & 15);
    const int acol = (lane >> 4) * 8;
    const int brow = (lane & 7) + ((lane >> 3) & 1) * 8;
    const int bcol = wn * 64 + ((lane >> 4) & 1) * 8;

    int cur = 0;
#pragma unroll 1
    for (int kc = 0; kc < 8; ++kc) {
        uint4 pa, yr[3]; uint32_t ye[3];
        float w0, w1, w2, v0, v1, v2;
        const bool more = (kc + 1) < 8;
        if (more) {
            pa = *(const uint4*)&g_f0h[(m0 + am) * 128 + (kc + 1) * 16 + akh];
            load_y(kc + 1, yr, ye, w0, w1, w2, v0, v1, v2);
        }

        uint32_t a[2][4];
        const uint32_t aS = aBase + cur * (128 * A_LD * 2);
#pragma unroll
        for (int mf = 0; mf < 2; ++mf)
            ldsm_x4(a[mf], aS + ((arow + mf * 16) * A_LD + acol) * 2);
        const uint32_t bS = bBase + cur * (16 * B3_LD * 2);
#pragma unroll
        for (int g = 0; g < 4; ++g) {
            uint32_t bf[4];
            ldsm_x4t(bf, bS + (brow * B3_LD + bcol + g * 16) * 2);
#pragma unroll
            for (int mf = 0; mf < 2; ++mf) {
                mma16816(acc[mf][g * 2 + 0], a[mf], bf + 0);
                mma16816(acc[mf][g * 2 + 1], a[mf], bf + 2);
            }
        }

        if (more) {
            int nxt = cur ^ 1;
            *(uint4*)&Ah[nxt * (128 * A_LD) + am * A_LD + akh] = pa;
            uint4 zw;
            compute_z(yr, ye, w0, w1, w2, v0, v1, v2, zw);
            *(uint4*)&Bh[nxt * (16 * B3_LD) + br * B3_LD + q8] = zw;
            __syncthreads();
            cur = nxt;
        }
    }

    // epilogue: stage fp32 tile, then contiguous float2 rows (no divides)
    __syncthreads();
    float* st = (float*)dsm;              // 128*ST_LD*4 = 67584 B
    const int r0 = wm * 32, n0 = wn * 64;
    const int lr = lane >> 2, lc = (lane & 3) * 2;
#pragma unroll
    for (int mf = 0; mf < 2; ++mf)
#pragma unroll
        for (int g = 0; g < 8; ++g) {
            int f = r0 + mf * 16 + lr;
            int q = n0 + g * 8 + lc;
            *(float2*)&st[f * ST_LD + q] = make_float2(acc[mf][g][0], acc[mf][g][1]);
            *(float2*)&st[(f + 8) * ST_LD + q] = make_float2(acc[mf][g][2], acc[mf][g][3]);
        }
    __syncthreads();
    {
        float* obase = out + ((size_t)(b * F_) + m0) * (HP * WP) + (size_t)p * WP;
        const int c2 = lane + 32;         // second-pass column
#pragma unroll 1
        for (int i = 0; i < 16; ++i) {
            int f = wid * 16 + i;
            const float* srow = &st[f * ST_LD];
            float* drow = obase + (size_t)f * (HP * WP);
            *(float2*)(drow + lane * 2) = *(const float2*)(srow + lane * 2);
            if (c2 < 63)
                *(float2*)(drow + c2 * 2) = *(const float2*)(srow + c2 * 2);
        }
    }
}

extern "C" void kernel_launch(void* const* d_in, const int* in_sizes, int n_in,
                              void* d_out, int out_size) {
    const float* x  = (const float*)d_in[0];
    const float* f0 = (const float*)d_in[1];
    const float* f1 = (const float*)d_in[2];
    const float* f2 = (const float*)d_in[3];
    const float* f3 = (const float*)d_in[4];
    float* out = (float*)d_out;

    cudaFuncSetAttribute(k1_mma, cudaFuncAttributeMaxDynamicSharedMemorySize,
                         DSMEM_BYTES);
    cudaFuncSetAttribute(k3_fused, cudaFuncAttributeMaxDynamicSharedMemorySize,
                         DSMEM_BYTES);

    ksplit_weights<<<128, 256>>>(f0, f3);
    k1_mma<<<dim3(H_ / 2, B_), 512, DSMEM_BYTES>>>(x);
    k3_fused<<<dim3(HP, 2, B_), 256, DSMEM_BYTES>>>(f1, f2, out);
}

// round 12
// speedup vs baseline: 1.0973x; 1.0973x over previous
#include <cuda_runtime.h>
#include <cuda_fp16.h>
#include <cstdint>

#define B_   32
#define C_   256
#define H_   128
#define W_   128
#define R_   128
#define F_   256
#define HP   126
#define WP   126
#define WPAD 128
#define HW_  (H_ * W_)

// ---- device scratch (allocation-free) -----------------------------------
__device__ __half g_yh[(size_t)B_ * R_ * H_ * W_];     // fp16 134 MB
__device__ __half g_zh[(size_t)B_ * R_ * HP * WPAD];   // fp16 132 MB
__device__ __half g_f3h[128 * 256];                    // f3^T [r][c]
__device__ __half g_f0h[256 * 128];                    // f0   [f][r]

// ---- PTX helpers --------------------------------------------------------
__device__ __forceinline__ uint32_t smem_u32(const void* p) {
    uint32_t a;
    asm("{ .reg .u64 t; cvta.to.shared.u64 t, %1; cvt.u32.u64 %0, t; }"
        : "=r"(a) : "l"(p));
    return a;
}
__device__ __forceinline__ void ldsm_x4(uint32_t* r, uint32_t addr) {
    asm volatile("ldmatrix.sync.aligned.m8n8.x4.shared.b16 {%0,%1,%2,%3}, [%4];"
                 : "=r"(r[0]), "=r"(r[1]), "=r"(r[2]), "=r"(r[3]) : "r"(addr));
}
__device__ __forceinline__ void ldsm_x4t(uint32_t* r, uint32_t addr) {
    asm volatile("ldmatrix.sync.aligned.m8n8.x4.trans.shared.b16 {%0,%1,%2,%3}, [%4];"
                 : "=r"(r[0]), "=r"(r[1]), "=r"(r[2]), "=r"(r[3]) : "r"(addr));
}
__device__ __forceinline__ void mma16816(float* c, const uint32_t* a,
                                         const uint32_t* b) {
    asm volatile(
        "mma.sync.aligned.m16n8k16.row.col.f32.f16.f16.f32 "
        "{%0,%1,%2,%3}, {%4,%5,%6,%7}, {%8,%9}, {%0,%1,%2,%3};"
        : "+f"(c[0]), "+f"(c[1]), "+f"(c[2]), "+f"(c[3])
        : "r"(a[0]), "r"(a[1]), "r"(a[2]), "r"(a[3]), "r"(b[0]), "r"(b[1]));
}
__device__ __forceinline__ void cp_async16(uint32_t dst, const void* src) {
    asm volatile("{ .reg .u64 g; cvta.to.global.u64 g, %1;"
                 "  cp.async.cg.shared.global [%0], [g], 16; }"
                 :: "r"(dst), "l"(src) : "memory");
}
#define CP_COMMIT() asm volatile("cp.async.commit_group;" ::: "memory")
#define CP_WAIT(n)  asm volatile("cp.async.wait_group %0;" :: "n"(n) : "memory")

__device__ __forceinline__ void stcs4(float* p, float4 v) {
    asm volatile("st.global.cs.v4.f32 [%0], {%1,%2,%3,%4};"
                 :: "l"(p), "f"(v.x), "f"(v.y), "f"(v.z), "f"(v.w) : "memory");
}
__device__ __forceinline__ void stcs2(float* p, float2 v) {
    asm volatile("st.global.cs.v2.f32 [%0], {%1,%2};"
                 :: "l"(p), "f"(v.x), "f"(v.y) : "memory");
}

#define A_LD  24    // halves per A smem row (16 + 8 pad) -> 48B stride
#define B3_LD 136   // K3 B row: 128 + 8 pad halves
#define B1_LD 264   // K1 B row: 256 + 8 pad halves
#define ST_LD 132   // floats per staged K3 output row

#define DSMEM_BYTES 69632   // 68 KB dynamic smem

// =========================================================================
// Setup: f0 -> fp16 [f][r] ; f3 transpose -> fp16 [r][c]
// =========================================================================
__global__ void ksplit_weights(const float* __restrict__ f0,
                               const float* __restrict__ f3) {
    int i = blockIdx.x * 256 + threadIdx.x;
    if (i < 256 * 128) g_f0h[i] = __float2half_rn(f0[i]);
    if (i < 128 * 256) {
        int m = i >> 8, k = i & 255;
        g_f3h[m * 256 + k] = __float2half_rn(f3[k * 128 + m]);
    }
}

// =========================================================================
// K1: y[b,r,h,w] = sum_c f3t[r,c] x[b,c,h,w]   (y fp16)
// block: M=128 (r), N=256 (2 h-rows), K=256, chunks of 16
// 512 threads, warps 4m x 4n, warp tile 32x64, 2-stage reg prefetch
// =========================================================================
__global__ __launch_bounds__(512, 1)
void k1_mma(const float* __restrict__ x) {
    extern __shared__ char dsm[];
    __half* Ah = (__half*)dsm;                 // 2 stages: 128*A_LD each
    __half* Bh = Ah + 2 * 128 * A_LD;          // 2 stages: 16*B1_LD each

    const int tid = threadIdx.x, wid = tid >> 5, lane = tid & 31;
    const int b = blockIdx.y, h0 = blockIdx.x * 2;
    const int wm = wid & 3, wn = wid >> 2;
    const float* xb = x + ((size_t)b * C_) * HW_ + (size_t)h0 * W_;

    float acc[2][8][4];
#pragma unroll
    for (int i = 0; i < 2; ++i)
#pragma unroll
        for (int j = 0; j < 8; ++j)
#pragma unroll
            for (int q = 0; q < 4; ++q) acc[i][j][q] = 0.f;

    const int am = tid >> 1, akh = (tid & 1) * 8;
    const int bk = tid >> 5, bn8 = (tid & 31) * 8;

    {
        if (tid < 256)
            *(uint4*)&Ah[am * A_LD + akh] = *(const uint4*)&g_f3h[am * 256 + akh];
        float4 v0 = *(const float4*)(xb + (size_t)bk * HW_ + bn8);
        float4 v1 = *(const float4*)(xb + (size_t)bk * HW_ + bn8 + 4);
        __half2 p0 = __floats2half2_rn(v0.x, v0.y), p1 = __floats2half2_rn(v0.z, v0.w);
        __half2 p2 = __floats2half2_rn(v1.x, v1.y), p3 = __floats2half2_rn(v1.z, v1.w);
        uint4 w = make_uint4(*(uint32_t*)&p0, *(uint32_t*)&p1,
                             *(uint32_t*)&p2, *(uint32_t*)&p3);
        *(uint4*)&Bh[bk * B1_LD + bn8] = w;
    }
    __syncthreads();

    const uint32_t aBase = smem_u32(Ah);
    const uint32_t bBase = smem_u32(Bh);
    const int arow = wm * 32 + (lane & 15);
    const int acol = (lane >> 4) * 8;
    const int brow = (lane & 7) + ((lane >> 3) & 1) * 8;
    const int bcol = wn * 64 + ((lane >> 4) & 1) * 8;

    int cur = 0;
#pragma unroll 1
    for (int kc = 0; kc < 16; ++kc) {
        uint4 pa; float4 pb0, pb1;
        const bool more = (kc + 1) < 16;
        if (more) {
            int c0n = (kc + 1) * 16;
            if (tid < 256) pa = *(const uint4*)&g_f3h[am * 256 + c0n + akh];
            pb0 = *(const float4*)(xb + (size_t)(c0n + bk) * HW_ + bn8);
            pb1 = *(const float4*)(xb + (size_t)(c0n + bk) * HW_ + bn8 + 4);
        }

        uint32_t a[2][4];
        const uint32_t aS = aBase + cur * (128 * A_LD * 2);
#pragma unroll
        for (int mf = 0; mf < 2; ++mf)
            ldsm_x4(a[mf], aS + ((arow + mf * 16) * A_LD + acol) * 2);
        const uint32_t bS = bBase + cur * (16 * B1_LD * 2);
#pragma unroll
        for (int g = 0; g < 4; ++g) {
            uint32_t bf[4];
            ldsm_x4t(bf, bS + (brow * B1_LD + bcol + g * 16) * 2);
#pragma unroll
            for (int mf = 0; mf < 2; ++mf) {
                mma16816(acc[mf][g * 2 + 0], a[mf], bf + 0);
                mma16816(acc[mf][g * 2 + 1], a[mf], bf + 2);
            }
        }

        if (more) {
            int nxt = cur ^ 1;
            if (tid < 256) *(uint4*)&Ah[nxt * (128 * A_LD) + am * A_LD + akh] = pa;
            __half2 p0 = __floats2half2_rn(pb0.x, pb0.y), p1 = __floats2half2_rn(pb0.z, pb0.w);
            __half2 p2 = __floats2half2_rn(pb1.x, pb1.y), p3 = __floats2half2_rn(pb1.z, pb1.w);
            uint4 w = make_uint4(*(uint32_t*)&p0, *(uint32_t*)&p1,
                                 *(uint32_t*)&p2, *(uint32_t*)&p3);
            *(uint4*)&Bh[nxt * (16 * B1_LD) + bk * B1_LD + bn8] = w;
            __syncthreads();
            cur = nxt;
        }
    }

    // epilogue: stage (128 r x 256 n halves), then 512B contiguous rows
    __syncthreads();
    __half* sy = (__half*)dsm;            // 128*B1_LD*2 = 67584 B
    const int r0 = wm * 32, n0 = wn * 64;
    const int lr = lane >> 2, lc = (lane & 3) * 2;
#pragma unroll
    for (int mf = 0; mf < 2; ++mf)
#pragma unroll
        for (int g = 0; g < 8; ++g) {
            int r = r0 + mf * 16 + lr;
            int n = n0 + g * 8 + lc;
            __half2 v0 = __floats2half2_rn(acc[mf][g][0], acc[mf][g][1]);
            __half2 v1 = __floats2half2_rn(acc[mf][g][2], acc[mf][g][3]);
            *(__half2*)&sy[r * B1_LD + n] = v0;
            *(__half2*)&sy[(r + 8) * B1_LD + n] = v1;
        }
    __syncthreads();
#pragma unroll
    for (int i = 0; i < 8; ++i) {
        int r = wid * 8 + i;
        uint4 v = *(const uint4*)&sy[r * B1_LD + lane * 8];
        *(uint4*)(g_yh + (((size_t)b * R_ + r) * H_ + h0) * W_ + lane * 8) = v;
    }
}

// =========================================================================
// K2: separable depthwise, y fp16 -> z fp16, 8 outputs/thread, 16B stores
// =========================================================================
__global__ __launch_bounds__(256)
void k2_depthwise(const float* __restrict__ f1, const float* __restrict__ f2) {
    const int tid = threadIdx.x;
    const int qi = tid & 15, psub = tid >> 4;
    const int p = blockIdx.x * 16 + psub;
    const int r = blockIdx.y, b = blockIdx.z;
    if (p >= HP) return;

    const float w0 = f2[r], w1 = f2[128 + r], w2 = f2[256 + r];
    const float v0 = f1[r], v1 = f1[128 + r], v2 = f1[256 + r];

    const __half* yb = g_yh + ((((size_t)b * R_) + r) * H_ + p) * W_;
    const int q0 = qi * 8;

    float z[8];
#pragma unroll
    for (int j = 0; j < 8; ++j) z[j] = 0.f;

#pragma unroll
    for (int a = 0; a < 3; ++a) {
        const __half* row = yb + a * W_ + q0;
        float t[10];
        uint4 raw = *(const uint4*)row;
        __half2* hp = (__half2*)&raw;
#pragma unroll
        for (int j = 0; j < 4; ++j) {
            float2 f = __half22float2(hp[j]);
            t[j * 2] = f.x; t[j * 2 + 1] = f.y;
        }
        if (q0 < 120) {
            float2 f = __half22float2(*(const __half2*)(row + 8));
            t[8] = f.x; t[9] = f.y;
        } else { t[8] = 0.f; t[9] = 0.f; }
        const float va = (a == 0) ? v0 : ((a == 1) ? v1 : v2);
#pragma unroll
        for (int j = 0; j < 8; ++j)
            z[j] += va * (t[j] * w0 + t[j + 1] * w1 + t[j + 2] * w2);
    }
    if (q0 == 120) { z[6] = 0.f; z[7] = 0.f; }

    __half2 o0 = __floats2half2_rn(z[0], z[1]), o1 = __floats2half2_rn(z[2], z[3]);
    __half2 o2 = __floats2half2_rn(z[4], z[5]), o3 = __floats2half2_rn(z[6], z[7]);
    uint4 w = make_uint4(*(uint32_t*)&o0, *(uint32_t*)&o1,
                         *(uint32_t*)&o2, *(uint32_t*)&o3);
    *(uint4*)(g_zh + ((((size_t)b * R_) + r) * HP + p) * WPAD + q0) = w;
}

// =========================================================================
// K3: out[b,f,p,q] = sum_r f0[f,r] z[b,r,p,q]
// block: 256 threads, warps 4m x 2n, warp tile 32x64, tile 128x128,
// K=128 chunks of 16, 4-stage cp.async.
// Epilogue: stage fp32 tile in smem, then p-parity-aligned 16B streaming
// stores (31 x STG.128 + 1 x STG.64 per row).
// =========================================================================
__global__ __launch_bounds__(256, 2)
void k3_mma(float* __restrict__ out) {
    extern __shared__ char dsm[];
    __half* Asm = (__half*)dsm;                 // 4 stages: 128*A_LD
    __half* Bsm = Asm + 4 * 128 * A_LD;         // 4 stages: 16*B3_LD

    const int tid = threadIdx.x, wid = tid >> 5, lane = tid & 31;
    const int p = blockIdx.x, m0 = blockIdx.y * 128, b = blockIdx.z;
    const int wm = wid & 3, wn = wid >> 2;
    const __half* zb = g_zh + ((size_t)b * R_ * HP + p) * WPAD;
    const size_t zks = (size_t)HP * WPAD;

    float acc[2][8][4];
#pragma unroll
    for (int i = 0; i < 2; ++i)
#pragma unroll
        for (int j = 0; j < 8; ++j)
#pragma unroll
            for (int q = 0; q < 4; ++q) acc[i][j][q] = 0.f;

    const int ar = tid >> 1, asg = (tid & 1) * 8;
    const int br = tid >> 4, bsg = (tid & 15) * 8;

#define K3_ISSUE(kc, st)                                                      \
    do {                                                                      \
        int k0_ = (kc) * 16;                                                  \
        cp_async16(smem_u32(&Asm[(st) * (128 * A_LD) + ar * A_LD + asg]),     \
                   g_f0h + (size_t)(m0 + ar) * 128 + k0_ + asg);              \
        cp_async16(smem_u32(&Bsm[(st) * (16 * B3_LD) + br * B3_LD + bsg]),    \
                   zb + (size_t)(k0_ + br) * zks + bsg);                      \
        CP_COMMIT();                                                          \
    } while (0)

    K3_ISSUE(0, 0);
    K3_ISSUE(1, 1);
    K3_ISSUE(2, 2);

    const uint32_t aBase = smem_u32(Asm);
    const uint32_t bBase = smem_u32(Bsm);
    const int arow = wm * 32 + (lane & 15);
    const int acol = (lane >> 4) * 8;
    const int brow = (lane & 7) + ((lane >> 3) & 1) * 8;
    const int bcol = wn * 64 + ((lane >> 4) & 1) * 8;

#pragma unroll 1
    for (int kc = 0; kc < 8; ++kc) {
        if (kc <= 5) CP_WAIT(2);
        else if (kc == 6) CP_WAIT(1);
        else CP_WAIT(0);
        __syncthreads();
        if (kc + 3 < 8) K3_ISSUE(kc + 3, (kc + 3) & 3);

        const int s = kc & 3;
        uint32_t a[2][4];
        const uint32_t aS = aBase + s * (128 * A_LD * 2);
#pragma unroll
        for (int mf = 0; mf < 2; ++mf)
            ldsm_x4(a[mf], aS + ((arow + mf * 16) * A_LD + acol) * 2);
        const uint32_t bS = bBase + s * (16 * B3_LD * 2);
#pragma unroll
        for (int g = 0; g < 4; ++g) {
            uint32_t bf[4];
            ldsm_x4t(bf, bS + (brow * B3_LD + bcol + g * 16) * 2);
#pragma unroll
            for (int mf = 0; mf < 2; ++mf) {
                mma16816(acc[mf][g * 2 + 0], a[mf], bf + 0);
                mma16816(acc[mf][g * 2 + 1], a[mf], bf + 2);
            }
        }
    }

    // ---- epilogue: stage tile, then p-parity-aligned 16B streaming stores -
    __syncthreads();
    float* st = (float*)dsm;              // 128*ST_LD*4 = 67584 B
    const int r0 = wm * 32, n0 = wn * 64;
    const int lr = lane >> 2, lc = (lane & 3) * 2;
#pragma unroll
    for (int mf = 0; mf < 2; ++mf)
#pragma unroll
        for (int g = 0; g < 8; ++g) {
            int f = r0 + mf * 16 + lr;
            int q = n0 + g * 8 + lc;
            *(float2*)&st[f * ST_LD + q] = make_float2(acc[mf][g][0], acc[mf][g][1]);
            *(float2*)&st[(f + 8) * ST_LD + q] = make_float2(acc[mf][g][2], acc[mf][g][3]);
        }
    __syncthreads();
    {
        float* obase = out + ((size_t)(b * F_) + m0) * (HP * WP) + (size_t)p * WP;
        const bool peven = (p & 1) == 0;
#pragma unroll 1
        for (int i = 0; i < 16; ++i) {
            int f = wid * 16 + i;
            const float* srow = &st[f * ST_LD];
            float* drow = obase + (size_t)f * (HP * WP);
            if (peven) {
                if (lane < 31) {
                    int q = lane * 4;                       // 0..120, 16B aligned
                    float4 v;
                    float2 a2 = *(const float2*)(srow + q);
                    float2 b2 = *(const float2*)(srow + q + 2);
                    v.x = a2.x; v.y = a2.y; v.z = b2.x; v.w = b2.y;
                    stcs4(drow + q, v);
                } else {
                    stcs2(drow + 124, *(const float2*)(srow + 124));
                }
            } else {
                if (lane < 31) {
                    int q = 2 + lane * 4;                   // 2..122, dst 16B aligned
                    float4 v;
                    float2 a2 = *(const float2*)(srow + q);
                    float2 b2 = *(const float2*)(srow + q + 2);
                    v.x = a2.x; v.y = a2.y; v.z = b2.x; v.w = b2.y;
                    stcs4(drow + q, v);
                } else {
                    stcs2(drow, *(const float2*)srow);
                }
            }
        }
    }
}

extern "C" void kernel_launch(void* const* d_in, const int* in_sizes, int n_in,
                              void* d_out, int out_size) {
    const float* x  = (const float*)d_in[0];
    const float* f0 = (const float*)d_in[1];
    const float* f1 = (const float*)d_in[2];
    const float* f2 = (const float*)d_in[3];
    const float* f3 = (const float*)d_in[4];
    float* out = (float*)d_out;

    cudaFuncSetAttribute(k1_mma, cudaFuncAttributeMaxDynamicSharedMemorySize,
                         DSMEM_BYTES);
    cudaFuncSetAttribute(k3_mma, cudaFuncAttributeMaxDynamicSharedMemorySize,
                         DSMEM_BYTES);

    ksplit_weights<<<128, 256>>>(f0, f3);
    k1_mma<<<dim3(H_ / 2, B_), 512, DSMEM_BYTES>>>(x);
    k2_depthwise<<<dim3(8, R_, B_), 256>>>(f1, f2);
    k3_mma<<<dim3(HP, 2, B_), 256, DSMEM_BYTES>>>(out);
}

// round 15
// speedup vs baseline: 1.1978x; 1.0916x over previous
#include <cuda_runtime.h>
#include <cuda_fp16.h>
#include <cstdint>

#define B_   32
#define C_   256
#define H_   128
#define W_   128
#define R_   128
#define F_   256
#define HP   126
#define WP   126
#define WPAD 128
#define HW_  (H_ * W_)

// ---- device scratch (allocation-free) -----------------------------------
__device__ __half g_yh[(size_t)B_ * R_ * H_ * W_];     // fp16 134 MB
__device__ __half g_zh[(size_t)B_ * R_ * HP * WPAD];   // fp16 132 MB
__device__ __half g_f3h[128 * 256];                    // f3^T [r][c]
__device__ __half g_f0h[256 * 128];                    // f0   [f][r]

// ---- PTX helpers --------------------------------------------------------
__device__ __forceinline__ uint32_t smem_u32(const void* p) {
    uint32_t a;
    asm("{ .reg .u64 t; cvta.to.shared.u64 t, %1; cvt.u32.u64 %0, t; }"
        : "=r"(a) : "l"(p));
    return a;
}
__device__ __forceinline__ void ldsm_x4(uint32_t* r, uint32_t addr) {
    asm volatile("ldmatrix.sync.aligned.m8n8.x4.shared.b16 {%0,%1,%2,%3}, [%4];"
                 : "=r"(r[0]), "=r"(r[1]), "=r"(r[2]), "=r"(r[3]) : "r"(addr));
}
__device__ __forceinline__ void ldsm_x4t(uint32_t* r, uint32_t addr) {
    asm volatile("ldmatrix.sync.aligned.m8n8.x4.trans.shared.b16 {%0,%1,%2,%3}, [%4];"
                 : "=r"(r[0]), "=r"(r[1]), "=r"(r[2]), "=r"(r[3]) : "r"(addr));
}
__device__ __forceinline__ void mma16816(float* c, const uint32_t* a,
                                         const uint32_t* b) {
    asm volatile(
        "mma.sync.aligned.m16n8k16.row.col.f32.f16.f16.f32 "
        "{%0,%1,%2,%3}, {%4,%5,%6,%7}, {%8,%9}, {%0,%1,%2,%3};"
        : "+f"(c[0]), "+f"(c[1]), "+f"(c[2]), "+f"(c[3])
        : "r"(a[0]), "r"(a[1]), "r"(a[2]), "r"(a[3]), "r"(b[0]), "r"(b[1]));
}
__device__ __forceinline__ void cp_async16(uint32_t dst, const void* src) {
    asm volatile("{ .reg .u64 g; cvta.to.global.u64 g, %1;"
                 "  cp.async.cg.shared.global [%0], [g], 16; }"
                 :: "r"(dst), "l"(src) : "memory");
}
#define CP_COMMIT() asm volatile("cp.async.commit_group;" ::: "memory")
#define CP_WAIT(n)  asm volatile("cp.async.wait_group %0;" :: "n"(n) : "memory")

__device__ __forceinline__ void stcs4(float* p, float4 v) {
    asm volatile("st.global.cs.v4.f32 [%0], {%1,%2,%3,%4};"
                 :: "l"(p), "f"(v.x), "f"(v.y), "f"(v.z), "f"(v.w) : "memory");
}
__device__ __forceinline__ void stcs2(float* p, float2 v) {
    asm volatile("st.global.cs.v2.f32 [%0], {%1,%2};"
                 :: "l"(p), "f"(v.x), "f"(v.y) : "memory");
}

#define A_LD  24    // halves per A smem row (16 + 8 pad) -> 48B stride
#define B3_LD 136   // K3 B row: 128 + 8 pad halves
#define B1_LD 264   // K1 fp16 B row: 256 + 8 pad halves
#define BF_LD 264   // K1 fp32 B stage row: floats
#define ST_LD 132   // floats per staged K3 output row

// K1 smem layout (bytes):
//  Bf32: 5 stages x 16*BF_LD*4 = 84480
//  A:    5 stages x 128*A_LD*2 = 30720
//  fb:   2 bufs   x 16*B1_LD*2 = 16896
#define K1_BF_BYTES (16 * BF_LD * 4)
#define K1_A_BYTES  (128 * A_LD * 2)
#define K1_FB_BYTES (16 * B1_LD * 2)
#define K1_A_OFF    (5 * K1_BF_BYTES)
#define K1_FB_OFF   (K1_A_OFF + 5 * K1_A_BYTES)
#define K1_DSMEM    (K1_FB_OFF + 2 * K1_FB_BYTES)   // 132096

#define K3_DSMEM 69632

// =========================================================================
// Setup: f0 -> fp16 [f][r] ; f3 transpose -> fp16 [r][c]
// =========================================================================
__global__ void ksplit_weights(const float* __restrict__ f0,
                               const float* __restrict__ f3) {
    int i = blockIdx.x * 256 + threadIdx.x;
    if (i < 256 * 128) g_f0h[i] = __float2half_rn(f0[i]);
    if (i < 128 * 256) {
        int m = i >> 8, k = i & 255;
        g_f3h[m * 256 + k] = __float2half_rn(f3[k * 128 + m]);
    }
}

// =========================================================================
// K1: y[b,r,h,w] = sum_c f3t[r,c] x[b,c,h,w]   (y fp16)
// M=128 (r), N=256 (2 h-rows), K=256, chunks of 16.
// 512 threads, warps 4m x 4n, warp tile 32x64.
// 5-stage cp.async of raw fp32 x -> smem, in-smem convert to fp16 double buf.
// =========================================================================
__global__ __launch_bounds__(512, 1)
void k1_mma(const float* __restrict__ x) {
    extern __shared__ char dsm[];
    float*  Bf = (float*)dsm;
    __half* Ah = (__half*)(dsm + K1_A_OFF);
    __half* fb = (__half*)(dsm + K1_FB_OFF);

    const int tid = threadIdx.x, wid = tid >> 5, lane = tid & 31;
    const int b = blockIdx.y, h0 = blockIdx.x * 2;
    const int wm = wid & 3, wn = wid >> 2;
    const float* xb = x + ((size_t)b * C_) * HW_ + (size_t)h0 * W_;

    float acc[2][8][4];
#pragma unroll
    for (int i = 0; i < 2; ++i)
#pragma unroll
        for (int j = 0; j < 8; ++j)
#pragma unroll
            for (int q = 0; q < 4; ++q) acc[i][j][q] = 0.f;

    // cp.async roles
    const int bk0 = tid >> 6, bc4 = (tid & 63) * 4;   // B: 2 segs (k, k+8)
    const int am = tid >> 1, akh = (tid & 1) * 8;     // A: 1 seg (tid<256)

#define K1_ISSUE(kc, st)                                                       \
    do {                                                                       \
        int k0_ = (kc) * 16;                                                   \
        uint32_t bfS = smem_u32(Bf) + (st) * K1_BF_BYTES;                      \
        cp_async16(bfS + (bk0 * BF_LD + bc4) * 4,                              \
                   xb + (size_t)(k0_ + bk0) * HW_ + bc4);                      \
        cp_async16(bfS + ((bk0 + 8) * BF_LD + bc4) * 4,                        \
                   xb + (size_t)(k0_ + bk0 + 8) * HW_ + bc4);                  \
        if (tid < 256)                                                         \
            cp_async16(smem_u32(Ah) + (st) * K1_A_BYTES + (am * A_LD + akh) * 2,\
                       g_f3h + am * 256 + k0_ + akh);                          \
        CP_COMMIT();                                                           \
    } while (0)

    // convert fp32 stage -> fp16 buffer (8 floats/thread)
    const int ck = tid >> 5, cc = (tid & 31) * 8;
#define K1_CONVERT(st, buf)                                                    \
    do {                                                                       \
        const float* srow = Bf + (st) * (16 * BF_LD) + ck * BF_LD + cc;        \
        float4 v0 = *(const float4*)srow;                                      \
        float4 v1 = *(const float4*)(srow + 4);                                \
        __half2 p0 = __floats2half2_rn(v0.x, v0.y);                            \
        __half2 p1 = __floats2half2_rn(v0.z, v0.w);                            \
        __half2 p2 = __floats2half2_rn(v1.x, v1.y);                            \
        __half2 p3 = __floats2half2_rn(v1.z, v1.w);                            \
        uint4 w = make_uint4(*(uint32_t*)&p0, *(uint32_t*)&p1,                 \
                             *(uint32_t*)&p2, *(uint32_t*)&p3);                \
        *(uint4*)&fb[(buf) * (16 * B1_LD) + ck * B1_LD + cc] = w;              \
    } while (0)

    // prologue: issue stages 0..3, convert chunk 0
    K1_ISSUE(0, 0); K1_ISSUE(1, 1); K1_ISSUE(2, 2); K1_ISSUE(3, 3);
    CP_WAIT(3);
    __syncthreads();
    K1_CONVERT(0, 0);

    const uint32_t aBase = smem_u32(Ah);
    const uint32_t fBase = smem_u32(fb);
    const int arow = wm * 32 + (lane & 15);
    const int acol = (lane >> 4) * 8;
    const int brow = (lane & 7) + ((lane >> 3) & 1) * 8;
    const int bcol = wn * 64 + ((lane >> 4) & 1) * 8;

    int cur = 0;
    int s_cur = 0, s_cvt = 1, s_iss = 4;
#pragma unroll 1
    for (int kc = 0; kc < 16; ++kc) {
        if (kc <= 12) CP_WAIT(2);
        else if (kc == 13) CP_WAIT(1);
        else CP_WAIT(0);
        __syncthreads();

        if (kc + 4 < 16) K1_ISSUE(kc + 4, s_iss);
        if (kc + 1 < 16) K1_CONVERT(s_cvt, cur ^ 1);

        uint32_t a[2][4];
        const uint32_t aS = aBase + s_cur * K1_A_BYTES;
#pragma unroll
        for (int mf = 0; mf < 2; ++mf)
            ldsm_x4(a[mf], aS + ((arow + mf * 16) * A_LD + acol) * 2);
        const uint32_t bS = fBase + cur * K1_FB_BYTES;
#pragma unroll
        for (int g = 0; g < 4; ++g) {
            uint32_t bf4[4];
            ldsm_x4t(bf4, bS + (brow * B1_LD + bcol + g * 16) * 2);
#pragma unroll
            for (int mf = 0; mf < 2; ++mf) {
                mma16816(acc[mf][g * 2 + 0], a[mf], bf4 + 0);
                mma16816(acc[mf][g * 2 + 1], a[mf], bf4 + 2);
            }
        }

        cur ^= 1;
        s_cur = (s_cur == 4) ? 0 : s_cur + 1;
        s_cvt = (s_cvt == 4) ? 0 : s_cvt + 1;
        s_iss = (s_iss == 4) ? 0 : s_iss + 1;
    }

    // epilogue: stage (128 r x 256 n halves), then 512B contiguous rows
    __syncthreads();
    __half* sy = (__half*)dsm;            // 128*B1_LD*2 = 67584 B
    const int r0 = wm * 32, n0 = wn * 64;
    const int lr = lane >> 2, lc = (lane & 3) * 2;
#pragma unroll
    for (int mf = 0; mf < 2; ++mf)
#pragma unroll
        for (int g = 0; g < 8; ++g) {
            int r = r0 + mf * 16 + lr;
            int n = n0 + g * 8 + lc;
            __half2 v0 = __floats2half2_rn(acc[mf][g][0], acc[mf][g][1]);
            __half2 v1 = __floats2half2_rn(acc[mf][g][2], acc[mf][g][3]);
            *(__half2*)&sy[r * B1_LD + n] = v0;
            *(__half2*)&sy[(r + 8) * B1_LD + n] = v1;
        }
    __syncthreads();
#pragma unroll
    for (int i = 0; i < 8; ++i) {
        int r = wid * 8 + i;
        uint4 v = *(const uint4*)&sy[r * B1_LD + lane * 8];
        *(uint4*)(g_yh + (((size_t)b * R_ + r) * H_ + h0) * W_ + lane * 8) = v;
    }
}

// =========================================================================
// K2: separable depthwise, y fp16 -> z fp16, 8 outputs/thread, 16B stores
// =========================================================================
__global__ __launch_bounds__(256)
void k2_depthwise(const float* __restrict__ f1, const float* __restrict__ f2) {
    const int tid = threadIdx.x;
    const int qi = tid & 15, psub = tid >> 4;
    const int p = blockIdx.x * 16 + psub;
    const int r = blockIdx.y, b = blockIdx.z;
    if (p >= HP) return;

    const float w0 = f2[r], w1 = f2[128 + r], w2 = f2[256 + r];
    const float v0 = f1[r], v1 = f1[128 + r], v2 = f1[256 + r];

    const __half* yb = g_yh + ((((size_t)b * R_) + r) * H_ + p) * W_;
    const int q0 = qi * 8;

    float z[8];
#pragma unroll
    for (int j = 0; j < 8; ++j) z[j] = 0.f;

#pragma unroll
    for (int a = 0; a < 3; ++a) {
        const __half* row = yb + a * W_ + q0;
        float t[10];
        uint4 raw = *(const uint4*)row;
        __half2* hp = (__half2*)&raw;
#pragma unroll
        for (int j = 0; j < 4; ++j) {
            float2 f = __half22float2(hp[j]);
            t[j * 2] = f.x; t[j * 2 + 1] = f.y;
        }
        if (q0 < 120) {
            float2 f = __half22float2(*(const __half2*)(row + 8));
            t[8] = f.x; t[9] = f.y;
        } else { t[8] = 0.f; t[9] = 0.f; }
        const float va = (a == 0) ? v0 : ((a == 1) ? v1 : v2);
#pragma unroll
        for (int j = 0; j < 8; ++j)
            z[j] += va * (t[j] * w0 + t[j + 1] * w1 + t[j + 2] * w2);
    }
    if (q0 == 120) { z[6] = 0.f; z[7] = 0.f; }

    __half2 o0 = __floats2half2_rn(z[0], z[1]), o1 = __floats2half2_rn(z[2], z[3]);
    __half2 o2 = __floats2half2_rn(z[4], z[5]), o3 = __floats2half2_rn(z[6], z[7]);
    uint4 w = make_uint4(*(uint32_t*)&o0, *(uint32_t*)&o1,
                         *(uint32_t*)&o2, *(uint32_t*)&o3);
    *(uint4*)(g_zh + ((((size_t)b * R_) + r) * HP + p) * WPAD + q0) = w;
}

// =========================================================================
// K3: out[b,f,p,q] = sum_r f0[f,r] z[b,r,p,q]
// 256 threads, warps 4m x 2n, warp tile 32x64, tile 128x128,
// K=128 chunks of 16, 4-stage cp.async; p-parity-aligned 16B .cs stores.
// =========================================================================
__global__ __launch_bounds__(256, 2)
void k3_mma(float* __restrict__ out) {
    extern __shared__ char dsm[];
    __half* Asm = (__half*)dsm;                 // 4 stages: 128*A_LD
    __half* Bsm = Asm + 4 * 128 * A_LD;         // 4 stages: 16*B3_LD

    const int tid = threadIdx.x, wid = tid >> 5, lane = tid & 31;
    const int p = blockIdx.x, m0 = blockIdx.y * 128, b = blockIdx.z;
    const int wm = wid & 3, wn = wid >> 2;
    const __half* zb = g_zh + ((size_t)b * R_ * HP + p) * WPAD;
    const size_t zks = (size_t)HP * WPAD;

    float acc[2][8][4];
#pragma unroll
    for (int i = 0; i < 2; ++i)
#pragma unroll
        for (int j = 0; j < 8; ++j)
#pragma unroll
            for (int q = 0; q < 4; ++q) acc[i][j][q] = 0.f;

    const int ar = tid >> 1, asg = (tid & 1) * 8;
    const int br = tid >> 4, bsg = (tid & 15) * 8;

#define K3_ISSUE(kc, st)                                                      \
    do {                                                                      \
        int k0_ = (kc) * 16;                                                  \
        cp_async16(smem_u32(&Asm[(st) * (128 * A_LD) + ar * A_LD + asg]),     \
                   g_f0h + (size_t)(m0 + ar) * 128 + k0_ + asg);              \
        cp_async16(smem_u32(&Bsm[(st) * (16 * B3_LD) + br * B3_LD + bsg]),    \
                   zb + (size_t)(k0_ + br) * zks + bsg);                      \
        CP_COMMIT();                                                          \
    } while (0)

    K3_ISSUE(0, 0);
    K3_ISSUE(1, 1);
    K3_ISSUE(2, 2);

    const uint32_t aBase = smem_u32(Asm);
    const uint32_t bBase = smem_u32(Bsm);
    const int arow = wm * 32 + (lane & 15);
    const int acol = (lane >> 4) * 8;
    const int brow = (lane & 7) + ((lane >> 3) & 1) * 8;
    const int bcol = wn * 64 + ((lane >> 4) & 1) * 8;

#pragma unroll 1
    for (int kc = 0; kc < 8; ++kc) {
        if (kc <= 5) CP_WAIT(2);
        else if (kc == 6) CP_WAIT(1);
        else CP_WAIT(0);
        __syncthreads();
        if (kc + 3 < 8) K3_ISSUE(kc + 3, (kc + 3) & 3);

        const int s = kc & 3;
        uint32_t a[2][4];
        const uint32_t aS = aBase + s * (128 * A_LD * 2);
#pragma unroll
        for (int mf = 0; mf < 2; ++mf)
            ldsm_x4(a[mf], aS + ((arow + mf * 16) * A_LD + acol) * 2);
        const uint32_t bS = bBase + s * (16 * B3_LD * 2);
#pragma unroll
        for (int g = 0; g < 4; ++g) {
            uint32_t bf4[4];
            ldsm_x4t(bf4, bS + (brow * B3_LD + bcol + g * 16) * 2);
#pragma unroll
            for (int mf = 0; mf < 2; ++mf) {
                mma16816(acc[mf][g * 2 + 0], a[mf], bf4 + 0);
                mma16816(acc[mf][g * 2 + 1], a[mf], bf4 + 2);
            }
        }
    }

    // epilogue: stage tile, then p-parity-aligned 16B streaming stores
    __syncthreads();
    float* st = (float*)dsm;              // 128*ST_LD*4 = 67584 B
    const int r0 = wm * 32, n0 = wn * 64;
    const int lr = lane >> 2, lc = (lane & 3) * 2;
#pragma unroll
    for (int mf = 0; mf < 2; ++mf)
#pragma unroll
        for (int g = 0; g < 8; ++g) {
            int f = r0 + mf * 16 + lr;
            int q = n0 + g * 8 + lc;
            *(float2*)&st[f * ST_LD + q] = make_float2(acc[mf][g][0], acc[mf][g][1]);
            *(float2*)&st[(f + 8) * ST_LD + q] = make_float2(acc[mf][g][2], acc[mf][g][3]);
        }
    __syncthreads();
    {
        float* obase = out + ((size_t)(b * F_) + m0) * (HP * WP) + (size_t)p * WP;
        const bool peven = (p & 1) == 0;
#pragma unroll 1
        for (int i = 0; i < 16; ++i) {
            int f = wid * 16 + i;
            const float* srow = &st[f * ST_LD];
            float* drow = obase + (size_t)f * (HP * WP);
            if (peven) {
                if (lane < 31) {
                    int q = lane * 4;
                    float4 v;
                    float2 a2 = *(const float2*)(srow + q);
                    float2 b2 = *(const float2*)(srow + q + 2);
                    v.x = a2.x; v.y = a2.y; v.z = b2.x; v.w = b2.y;
                    stcs4(drow + q, v);
                } else {
                    stcs2(drow + 124, *(const float2*)(srow + 124));
                }
            } else {
                if (lane < 31) {
                    int q = 2 + lane * 4;
                    float4 v;
                    float2 a2 = *(const float2*)(srow + q);
                    float2 b2 = *(const float2*)(srow + q + 2);
                    v.x = a2.x; v.y = a2.y; v.z = b2.x; v.w = b2.y;
                    stcs4(drow + q, v);
                } else {
                    stcs2(drow, *(const float2*)srow);
                }
            }
        }
    }
}

extern "C" void kernel_launch(void* const* d_in, const int* in_sizes, int n_in,
                              void* d_out, int out_size) {
    const float* x  = (const float*)d_in[0];
    const float* f0 = (const float*)d_in[1];
    const float* f1 = (const float*)d_in[2];
    const float* f2 = (const float*)d_in[3];
    const float* f3 = (const float*)d_in[4];
    float* out = (float*)d_out;

    cudaFuncSetAttribute(k1_mma, cudaFuncAttributeMaxDynamicSharedMemorySize,
                         K1_DSMEM);
    cudaFuncSetAttribute(k3_mma, cudaFuncAttributeMaxDynamicSharedMemorySize,
                         K3_DSMEM);

    ksplit_weights<<<128, 256>>>(f0, f3);
    k1_mma<<<dim3(H_ / 2, B_), 512, K1_DSMEM>>>(x);
    k2_depthwise<<<dim3(8, R_, B_), 256>>>(f1, f2);
    k3_mma<<<dim3(HP, 2, B_), 256, K3_DSMEM>>>(out);
}

// round 17
// speedup vs baseline: 1.2142x; 1.0137x over previous
#include <cuda_runtime.h>
#include <cuda_fp16.h>
#include <cstdint>

#define B_   32
#define C_   256
#define H_   128
#define W_   128
#define R_   128
#define F_   256
#define HP   126
#define WP   126
#define WPAD 128
#define HW_  (H_ * W_)

// ---- device scratch (allocation-free) -----------------------------------
__device__ __half g_yh[(size_t)B_ * R_ * H_ * W_];     // fp16 134 MB
__device__ __half g_zh[(size_t)B_ * R_ * HP * WPAD];   // fp16 132 MB
__device__ __half g_f3h[128 * 256];                    // f3^T [r][c]
__device__ __half g_f0h[256 * 128];                    // f0   [f][r]

// ---- PTX helpers --------------------------------------------------------
__device__ __forceinline__ uint32_t smem_u32(const void* p) {
    uint32_t a;
    asm("{ .reg .u64 t; cvta.to.shared.u64 t, %1; cvt.u32.u64 %0, t; }"
        : "=r"(a) : "l"(p));
    return a;
}
__device__ __forceinline__ void ldsm_x4(uint32_t* r, uint32_t addr) {
    asm volatile("ldmatrix.sync.aligned.m8n8.x4.shared.b16 {%0,%1,%2,%3}, [%4];"
                 : "=r"(r[0]), "=r"(r[1]), "=r"(r[2]), "=r"(r[3]) : "r"(addr));
}
__device__ __forceinline__ void ldsm_x4t(uint32_t* r, uint32_t addr) {
    asm volatile("ldmatrix.sync.aligned.m8n8.x4.trans.shared.b16 {%0,%1,%2,%3}, [%4];"
                 : "=r"(r[0]), "=r"(r[1]), "=r"(r[2]), "=r"(r[3]) : "r"(addr));
}
__device__ __forceinline__ void mma16816(float* c, const uint32_t* a,
                                         const uint32_t* b) {
    asm volatile(
        "mma.sync.aligned.m16n8k16.row.col.f32.f16.f16.f32 "
        "{%0,%1,%2,%3}, {%4,%5,%6,%7}, {%8,%9}, {%0,%1,%2,%3};"
        : "+f"(c[0]), "+f"(c[1]), "+f"(c[2]), "+f"(c[3])
        : "r"(a[0]), "r"(a[1]), "r"(a[2]), "r"(a[3]), "r"(b[0]), "r"(b[1]));
}
__device__ __forceinline__ void cp_async16(uint32_t dst, const void* src) {
    asm volatile("{ .reg .u64 g; cvta.to.global.u64 g, %1;"
                 "  cp.async.cg.shared.global [%0], [g], 16; }"
                 :: "r"(dst), "l"(src) : "memory");
}
#define CP_COMMIT() asm volatile("cp.async.commit_group;" ::: "memory")
#define CP_WAIT(n)  asm volatile("cp.async.wait_group %0;" :: "n"(n) : "memory")

__device__ __forceinline__ void stcs4(float* p, float4 v) {
    asm volatile("st.global.cs.v4.f32 [%0], {%1,%2,%3,%4};"
                 :: "l"(p), "f"(v.x), "f"(v.y), "f"(v.z), "f"(v.w) : "memory");
}
__device__ __forceinline__ void stcs2(float* p, float2 v) {
    asm volatile("st.global.cs.v2.f32 [%0], {%1,%2};"
                 :: "l"(p), "f"(v.x), "f"(v.y) : "memory");
}

#define A_LD  24    // halves per A smem row (16 + 8 pad) -> 48B stride
#define B3_LD 136   // K3 B row: 128 + 8 pad halves
#define B1_LD 264   // K1 fp16 B row: 256 + 8 pad halves
#define BF_LD 264   // K1 fp32 B stage row: floats
#define ST_LD 132   // floats per staged K3 output row

// K1 smem layout (bytes): 7 fp32 B stages, 7 A stages, 2 fp16 B buffers
#define K1_BF_BYTES (16 * BF_LD * 4)      // 16896
#define K1_A_BYTES  (128 * A_LD * 2)      // 6144
#define K1_FB_BYTES (16 * B1_LD * 2)      // 8448
#define K1_A_OFF    (7 * K1_BF_BYTES)
#define K1_FB_OFF   (K1_A_OFF + 7 * K1_A_BYTES)
#define K1_DSMEM    (K1_FB_OFF + 2 * K1_FB_BYTES)   // 178176

#define K3_DSMEM 69632

// =========================================================================
// Setup: f0 -> fp16 [f][r] ; f3 transpose -> fp16 [r][c]
// =========================================================================
__global__ void ksplit_weights(const float* __restrict__ f0,
                               const float* __restrict__ f3) {
    int i = blockIdx.x * 256 + threadIdx.x;
    if (i < 256 * 128) g_f0h[i] = __float2half_rn(f0[i]);
    if (i < 128 * 256) {
        int m = i >> 8, k = i & 255;
        g_f3h[m * 256 + k] = __float2half_rn(f3[k * 128 + m]);
    }
}

// =========================================================================
// K1: y[b,r,h,w] = sum_c f3t[r,c] x[b,c,h,w]   (y fp16)
// M=128 (r), N=256 (2 h-rows), K=256, chunks of 16.
// 512 threads, warps 4m x 4n, warp tile 32x64.
// 7-stage cp.async of raw fp32 x -> smem, in-smem convert to fp16 double buf.
// Wait invariant: convert needs chunk kc+1 complete -> steady CP_WAIT(4).
// =========================================================================
__global__ __launch_bounds__(512, 1)
void k1_mma(const float* __restrict__ x) {
    extern __shared__ char dsm[];
    float*  Bf = (float*)dsm;
    __half* Ah = (__half*)(dsm + K1_A_OFF);
    __half* fb = (__half*)(dsm + K1_FB_OFF);

    const int tid = threadIdx.x, wid = tid >> 5, lane = tid & 31;
    const int b = blockIdx.y, h0 = blockIdx.x * 2;
    const int wm = wid & 3, wn = wid >> 2;
    const float* xb = x + ((size_t)b * C_) * HW_ + (size_t)h0 * W_;

    float acc[2][8][4];
#pragma unroll
    for (int i = 0; i < 2; ++i)
#pragma unroll
        for (int j = 0; j < 8; ++j)
#pragma unroll
            for (int q = 0; q < 4; ++q) acc[i][j][q] = 0.f;

    const int bk0 = tid >> 6, bc4 = (tid & 63) * 4;   // B: 2 segs (k, k+8)
    const int am = tid >> 1, akh = (tid & 1) * 8;     // A: 1 seg (tid<256)

#define K1_ISSUE(kc, st)                                                       \
    do {                                                                       \
        int k0_ = (kc) * 16;                                                   \
        uint32_t bfS = smem_u32(Bf) + (st) * K1_BF_BYTES;                      \
        cp_async16(bfS + (bk0 * BF_LD + bc4) * 4,                              \
                   xb + (size_t)(k0_ + bk0) * HW_ + bc4);                      \
        cp_async16(bfS + ((bk0 + 8) * BF_LD + bc4) * 4,                        \
                   xb + (size_t)(k0_ + bk0 + 8) * HW_ + bc4);                  \
        if (tid < 256)                                                         \
            cp_async16(smem_u32(Ah) + (st) * K1_A_BYTES + (am * A_LD + akh) * 2,\
                       g_f3h + am * 256 + k0_ + akh);                          \
        CP_COMMIT();                                                           \
    } while (0)

    const int ck = tid >> 5, cc = (tid & 31) * 8;
#define K1_CONVERT(st, buf)                                                    \
    do {                                                                       \
        const float* srow = Bf + (st) * (16 * BF_LD) + ck * BF_LD + cc;        \
        float4 v0 = *(const float4*)srow;                                      \
        float4 v1 = *(const float4*)(srow + 4);                                \
        __half2 p0 = __floats2half2_rn(v0.x, v0.y);                            \
        __half2 p1 = __floats2half2_rn(v0.z, v0.w);                            \
        __half2 p2 = __floats2half2_rn(v1.x, v1.y);                            \
        __half2 p3 = __floats2half2_rn(v1.z, v1.w);                            \
        uint4 w = make_uint4(*(uint32_t*)&p0, *(uint32_t*)&p1,                 \
                             *(uint32_t*)&p2, *(uint32_t*)&p3);                \
        *(uint4*)&fb[(buf) * (16 * B1_LD) + ck * B1_LD + cc] = w;              \
    } while (0)

    // prologue: issue stages 0..5, convert chunk 0
    K1_ISSUE(0, 0); K1_ISSUE(1, 1); K1_ISSUE(2, 2);
    K1_ISSUE(3, 3); K1_ISSUE(4, 4); K1_ISSUE(5, 5);
    CP_WAIT(5);                                   // chunk 0 complete
    __syncthreads();
    K1_CONVERT(0, 0);

    const uint32_t aBase = smem_u32(Ah);
    const uint32_t fBase = smem_u32(fb);
    const int arow = wm * 32 + (lane & 15);
    const int acol = (lane >> 4) * 8;
    const int brow = (lane & 7) + ((lane >> 3) & 1) * 8;
    const int bcol = wn * 64 + ((lane >> 4) & 1) * 8;

    int cur = 0;
    int s_cur = 0, s_cvt = 1, s_iss = 6;
#pragma unroll 1
    for (int kc = 0; kc < 16; ++kc) {
        // need chunk kc+1 complete for the convert-ahead:
        // committed = min(16, kc+6) groups -> pending <= committed-(kc+2)
        if (kc <= 10) CP_WAIT(4);
        else if (kc == 11) CP_WAIT(3);
        else if (kc == 12) CP_WAIT(2);
        else if (kc == 13) CP_WAIT(1);
        else CP_WAIT(0);
        __syncthreads();

        if (kc + 6 < 16) K1_ISSUE(kc + 6, s_iss);
        if (kc + 1 < 16) K1_CONVERT(s_cvt, cur ^ 1);

        uint32_t a[2][4];
        const uint32_t aS = aBase + s_cur * K1_A_BYTES;
#pragma unroll
        for (int mf = 0; mf < 2; ++mf)
            ldsm_x4(a[mf], aS + ((arow + mf * 16) * A_LD + acol) * 2);
        const uint32_t bS = fBase + cur * K1_FB_BYTES;
#pragma unroll
        for (int g = 0; g < 4; ++g) {
            uint32_t bf4[4];
            ldsm_x4t(bf4, bS + (brow * B1_LD + bcol + g * 16) * 2);
#pragma unroll
            for (int mf = 0; mf < 2; ++mf) {
                mma16816(acc[mf][g * 2 + 0], a[mf], bf4 + 0);
                mma16816(acc[mf][g * 2 + 1], a[mf], bf4 + 2);
            }
        }

        cur ^= 1;
        s_cur = (s_cur == 6) ? 0 : s_cur + 1;
        s_cvt = (s_cvt == 6) ? 0 : s_cvt + 1;
        s_iss = (s_iss == 6) ? 0 : s_iss + 1;
    }

    // epilogue: stage (128 r x 256 n halves), then 512B contiguous rows
    __syncthreads();
    __half* sy = (__half*)dsm;            // 128*B1_LD*2 = 67584 B
    const int r0 = wm * 32, n0 = wn * 64;
    const int lr = lane >> 2, lc = (lane & 3) * 2;
#pragma unroll
    for (int mf = 0; mf < 2; ++mf)
#pragma unroll
        for (int g = 0; g < 8; ++g) {
            int r = r0 + mf * 16 + lr;
            int n = n0 + g * 8 + lc;
            __half2 v0 = __floats2half2_rn(acc[mf][g][0], acc[mf][g][1]);
            __half2 v1 = __floats2half2_rn(acc[mf][g][2], acc[mf][g][3]);
            *(__half2*)&sy[r * B1_LD + n] = v0;
            *(__half2*)&sy[(r + 8) * B1_LD + n] = v1;
        }
    __syncthreads();
#pragma unroll
    for (int i = 0; i < 8; ++i) {
        int r = wid * 8 + i;
        uint4 v = *(const uint4*)&sy[r * B1_LD + lane * 8];
        *(uint4*)(g_yh + (((size_t)b * R_ + r) * H_ + h0) * W_ + lane * 8) = v;
    }
}

// =========================================================================
// K2: separable depthwise, y fp16 -> z fp16.
// Each thread: 4 consecutive p rows x 8 q, rolling horizontal-conv window.
// =========================================================================
__global__ __launch_bounds__(256)
void k2_depthwise(const float* __restrict__ f1, const float* __restrict__ f2) {
    const int tid = threadIdx.x;
    const int qi = tid & 15, pg = tid >> 4;
    const int p0 = blockIdx.x * 64 + pg * 4;   // 0..124
    const int r = blockIdx.y, b = blockIdx.z;
    if (p0 >= HP) return;

    const float w0 = f2[r], w1 = f2[128 + r], w2 = f2[256 + r];
    const float v0 = f1[r], v1 = f1[128 + r], v2 = f1[256 + r];

    const int q0 = qi * 8;
    const bool qedge = (q0 == 120);
    const __half* yb = g_yh + ((((size_t)b * R_) + r) * H_) * W_ + q0;
    __half* zp = g_zh + ((((size_t)b * R_) + r) * HP) * WPAD + q0;

    float hc[3][8];

    auto hrow = [&](int row, float* h) {
        const __half* rp = yb + row * W_;
        float t[10];
        uint4 raw = *(const uint4*)rp;
        const __half2* hp = (const __half2*)&raw;
#pragma unroll
        for (int j = 0; j < 4; ++j) {
            float2 f = __half22float2(hp[j]);
            t[j * 2] = f.x; t[j * 2 + 1] = f.y;
        }
        if (!qedge) {
            float2 f = __half22float2(*(const __half2*)(rp + 8));
            t[8] = f.x; t[9] = f.y;
        } else { t[8] = 0.f; t[9] = 0.f; }
#pragma unroll
        for (int j = 0; j < 8; ++j)
            h[j] = t[j] * w0 + t[j + 1] * w1 + t[j + 2] * w2;
    };

    hrow(p0, hc[0]);
    hrow(p0 + 1, hc[1]);

#pragma unroll
    for (int i = 0; i < 4; ++i) {
        const int p = p0 + i;
        if (p >= HP) break;
        hrow(p + 2, hc[(i + 2) % 3]);
        const float* h0 = hc[i % 3];
        const float* h1 = hc[(i + 1) % 3];
        const float* h2 = hc[(i + 2) % 3];
        float z[8];
#pragma unroll
        for (int j = 0; j < 8; ++j)
            z[j] = v0 * h0[j] + v1 * h1[j] + v2 * h2[j];
        if (qedge) { z[6] = 0.f; z[7] = 0.f; }

        __half2 o0 = __floats2half2_rn(z[0], z[1]), o1 = __floats2half2_rn(z[2], z[3]);
        __half2 o2 = __floats2half2_rn(z[4], z[5]), o3 = __floats2half2_rn(z[6], z[7]);
        uint4 w = make_uint4(*(uint32_t*)&o0, *(uint32_t*)&o1,
                             *(uint32_t*)&o2, *(uint32_t*)&o3);
        *(uint4*)(zp + (size_t)p * WPAD) = w;
    }
}

// =========================================================================
// K3: out[b,f,p,q] = sum_r f0[f,r] z[b,r,p,q]
// 256 threads, warps 4m x 2n, warp tile 32x64, tile 128x128,
// K=128 chunks of 16, 4-stage cp.async; p-parity-aligned 16B .cs stores.
// =========================================================================
__global__ __launch_bounds__(256, 2)
void k3_mma(float* __restrict__ out) {
    extern __shared__ char dsm[];
    __half* Asm = (__half*)dsm;                 // 4 stages: 128*A_LD
    __half* Bsm = Asm + 4 * 128 * A_LD;         // 4 stages: 16*B3_LD

    const int tid = threadIdx.x, wid = tid >> 5, lane = tid & 31;
    const int p = blockIdx.x, m0 = blockIdx.y * 128, b = blockIdx.z;
    const int wm = wid & 3, wn = wid >> 2;
    const __half* zb = g_zh + ((size_t)b * R_ * HP + p) * WPAD;
    const size_t zks = (size_t)HP * WPAD;

    float acc[2][8][4];
#pragma unroll
    for (int i = 0; i < 2; ++i)
#pragma unroll
        for (int j = 0; j < 8; ++j)
#pragma unroll
            for (int q = 0; q < 4; ++q) acc[i][j][q] = 0.f;

    const int ar = tid >> 1, asg = (tid & 1) * 8;
    const int br = tid >> 4, bsg = (tid & 15) * 8;

#define K3_ISSUE(kc, st)                                                      \
    do {                                                                      \
        int k0_ = (kc) * 16;                                                  \
        cp_async16(smem_u32(&Asm[(st) * (128 * A_LD) + ar * A_LD + asg]),     \
                   g_f0h + (size_t)(m0 + ar) * 128 + k0_ + asg);              \
        cp_async16(smem_u32(&Bsm[(st) * (16 * B3_LD) + br * B3_LD + bsg]),    \
                   zb + (size_t)(k0_ + br) * zks + bsg);                      \
        CP_COMMIT();                                                          \
    } while (0)

    K3_ISSUE(0, 0);
    K3_ISSUE(1, 1);
    K3_ISSUE(2, 2);

    const uint32_t aBase = smem_u32(Asm);
    const uint32_t bBase = smem_u32(Bsm);
    const int arow = wm * 32 + (lane & 15);
    const int acol = (lane >> 4) * 8;
    const int brow = (lane & 7) + ((lane >> 3) & 1) * 8;
    const int bcol = wn * 64 + ((lane >> 4) & 1) * 8;

#pragma unroll 1
    for (int kc = 0; kc < 8; ++kc) {
        if (kc <= 5) CP_WAIT(2);
        else if (kc == 6) CP_WAIT(1);
        else CP_WAIT(0);
        __syncthreads();
        if (kc + 3 < 8) K3_ISSUE(kc + 3, (kc + 3) & 3);

        const int s = kc & 3;
        uint32_t a[2][4];
        const uint32_t aS = aBase + s * (128 * A_LD * 2);
#pragma unroll
        for (int mf = 0; mf < 2; ++mf)
            ldsm_x4(a[mf], aS + ((arow + mf * 16) * A_LD + acol) * 2);
        const uint32_t bS = bBase + s * (16 * B3_LD * 2);
#pragma unroll
        for (int g = 0; g < 4; ++g) {
            uint32_t bf4[4];
            ldsm_x4t(bf4, bS + (brow * B3_LD + bcol + g * 16) * 2);
#pragma unroll
            for (int mf = 0; mf < 2; ++mf) {
                mma16816(acc[mf][g * 2 + 0], a[mf], bf4 + 0);
                mma16816(acc[mf][g * 2 + 1], a[mf], bf4 + 2);
            }
        }
    }

    // epilogue: stage tile, then p-parity-aligned 16B streaming stores
    __syncthreads();
    float* st = (float*)dsm;              // 128*ST_LD*4 = 67584 B
    const int r0 = wm * 32, n0 = wn * 64;
    const int lr = lane >> 2, lc = (lane & 3) * 2;
#pragma unroll
    for (int mf = 0; mf < 2; ++mf)
#pragma unroll
        for (int g = 0; g < 8; ++g) {
            int f = r0 + mf * 16 + lr;
            int q = n0 + g * 8 + lc;
            *(float2*)&st[f * ST_LD + q] = make_float2(acc[mf][g][0], acc[mf][g][1]);
            *(float2*)&st[(f + 8) * ST_LD + q] = make_float2(acc[mf][g][2], acc[mf][g][3]);
        }
    __syncthreads();
    {
        float* obase = out + ((size_t)(b * F_) + m0) * (HP * WP) + (size_t)p * WP;
        const bool peven = (p & 1) == 0;
#pragma unroll 1
        for (int i = 0; i < 16; ++i) {
            int f = wid * 16 + i;
            const float* srow = &st[f * ST_LD];
            float* drow = obase + (size_t)f * (HP * WP);
            if (peven) {
                if (lane < 31) {
                    int q = lane * 4;
                    float4 v;
                    float2 a2 = *(const float2*)(srow + q);
                    float2 b2 = *(const float2*)(srow + q + 2);
                    v.x = a2.x; v.y = a2.y; v.z = b2.x; v.w = b2.y;
                    stcs4(drow + q, v);
                } else {
                    stcs2(drow + 124, *(const float2*)(srow + 124));
                }
            } else {
                if (lane < 31) {
                    int q = 2 + lane * 4;
                    float4 v;
                    float2 a2 = *(const float2*)(srow + q);
                    float2 b2 = *(const float2*)(srow + q + 2);
                    v.x = a2.x; v.y = a2.y; v.z = b2.x; v.w = b2.y;
                    stcs4(drow + q, v);
                } else {
                    stcs2(drow, *(const float2*)srow);
                }
            }
        }
    }
}

extern "C" void kernel_launch(void* const* d_in, const int* in_sizes, int n_in,
                              void* d_out, int out_size) {
    const float* x  = (const float*)d_in[0];
    const float* f0 = (const float*)d_in[1];
    const float* f1 = (const float*)d_in[2];
    const float* f2 = (const float*)d_in[3];
    const float* f3 = (const float*)d_in[4];
    float* out = (float*)d_out;

    cudaFuncSetAttribute(k1_mma, cudaFuncAttributeMaxDynamicSharedMemorySize,
                         K1_DSMEM);
    cudaFuncSetAttribute(k3_mma, cudaFuncAttributeMaxDynamicSharedMemorySize,
                         K3_DSMEM);

    ksplit_weights<<<128, 256>>>(f0, f3);
    k1_mma<<<dim3(H_ / 2, B_), 512, K1_DSMEM>>>(x);
    k2_depthwise<<<dim3(2, R_, B_), 256>>>(f1, f2);
    k3_mma<<<dim3(HP, 2, B_), 256, K3_DSMEM>>>(out);
}